// round 12
// baseline (speedup 1.0000x reference)
#include <cuda_runtime.h>
#include <cuda_bf16.h>
#include <cstdint>

#define BB 8
#define CC 768
#define HW 4096
#define CK 96
#define LL 6144   // CK * H
#define DD 64     // = W

// Scratch (device globals; no allocation allowed)
__device__ __nv_bfloat16 g_Qh[BB * LL * DD];
__device__ __nv_bfloat16 g_Kh[BB * LL * DD];
__device__ __nv_bfloat16 g_Vh[BB * LL * DD];
__device__ __nv_bfloat16 g_Ah[BB * LL * DD];
__device__ __nv_bfloat16 g_Wh[3 * CK * CC];   // Wq,Wk,Wv in bf16
__device__ __nv_bfloat16 g_Wch[CC * CK];      // Wc in bf16

// ---------------------------------------------------------------------------
// Helpers
// ---------------------------------------------------------------------------
__device__ __forceinline__ uint32_t smem_u32(const void* p) {
    return (uint32_t)__cvta_generic_to_shared(p);
}
__device__ __forceinline__ void ldsm_x4(uint32_t d[4], uint32_t a) {
    asm volatile("ldmatrix.sync.aligned.m8n8.x4.shared.b16 {%0,%1,%2,%3},[%4];"
                 : "=r"(d[0]), "=r"(d[1]), "=r"(d[2]), "=r"(d[3]) : "r"(a));
}
__device__ __forceinline__ void ldsm_x4_t(uint32_t d[4], uint32_t a) {
    asm volatile("ldmatrix.sync.aligned.m8n8.x4.trans.shared.b16 {%0,%1,%2,%3},[%4];"
                 : "=r"(d[0]), "=r"(d[1]), "=r"(d[2]), "=r"(d[3]) : "r"(a));
}
__device__ __forceinline__ void mma_bf16(float c[4], const uint32_t a[4], const uint32_t b[2]) {
    asm volatile(
        "mma.sync.aligned.m16n8k16.row.col.f32.bf16.bf16.f32 "
        "{%0,%1,%2,%3},{%4,%5,%6,%7},{%8,%9},{%0,%1,%2,%3};"
        : "+f"(c[0]), "+f"(c[1]), "+f"(c[2]), "+f"(c[3])
        : "r"(a[0]), "r"(a[1]), "r"(a[2]), "r"(a[3]), "r"(b[0]), "r"(b[1]));
}
__device__ __forceinline__ uint32_t packbf(float a, float b) {
    __nv_bfloat162 t = __floats2bfloat162_rn(a, b);
    return *(uint32_t*)&t;
}
__device__ __forceinline__ void cp16(uint32_t dst, const void* src) {
    asm volatile("cp.async.cg.shared.global [%0],[%1],16;" :: "r"(dst), "l"(src));
}
#define CP_COMMIT() asm volatile("cp.async.commit_group;" ::: "memory")
#define CP_WAIT0()  asm volatile("cp.async.wait_group 0;" ::: "memory")

// ---------------------------------------------------------------------------
// Prep: convert weights to bf16 once
// ---------------------------------------------------------------------------
__global__ void prep_kernel(const float* __restrict__ Wq, const float* __restrict__ Wk,
                            const float* __restrict__ Wv, const float* __restrict__ Wc)
{
    int i = blockIdx.x * 256 + threadIdx.x;
    const int n1 = 3 * CK * CC;
    if (i < n1) {
        int p = i / (CK * CC), r = i % (CK * CC);
        const float* W = (p == 0) ? Wq : (p == 1) ? Wk : Wv;
        g_Wh[i] = __float2bfloat16(W[r]);
    } else if (i < n1 + CC * CK) {
        g_Wch[i - n1] = __float2bfloat16(Wc[i - n1]);
    }
}

// ---------------------------------------------------------------------------
// Fused projection, double-buffered cp.async pipeline. (unchanged)
// ---------------------------------------------------------------------------
#define PJ_XF_OFF 82944
#define PJ_XS_OFF 148480
#define PJ_SMEM   165888
#define PJ_NKT    12

__global__ __launch_bounds__(384) void proj_kernel(const float* __restrict__ x)
{
    extern __shared__ char smem[];
    const uint32_t sb = smem_u32(smem);

    const int tid = threadIdx.x, warp = tid >> 5, lane = tid & 31;
    const int n0 = blockIdx.x * 128;
    const int b = blockIdx.z;
    const float* Xb = x + (size_t)b * CC * HW;

    const int mrow = (warp % 6) * 16;
    const int nh = (warp / 6) * 64;

    float Cacc[3][8][4];
#pragma unroll
    for (int p = 0; p < 3; p++)
#pragma unroll
        for (int d = 0; d < 8; d++)
#pragma unroll
            for (int q = 0; q < 4; q++) Cacc[p][d][q] = 0.f;

    const int arow = mrow + (lane & 15), acol = (lane >> 4) << 3;
    const int trow = (lane & 7) + (((lane >> 3) & 1) << 3);
    const int tcol = nh + ((lane >> 4) << 3);

    auto stage = [&](int kt, int buf) {
        const uint32_t wb = sb + buf * 41472;
        const uint32_t xf = sb + PJ_XF_OFF + buf * 32768;
#pragma unroll
        for (int idx = tid; idx < 2304; idx += 384) {
            int p = idx / 768, rem = idx - p * 768;
            int m = rem >> 3, f = rem & 7;
            cp16(wb + (p * 96 + m) * 144 + f * 16,
                 g_Wh + (size_t)(p * CK + m) * CC + kt + f * 8);
        }
        for (int idx = tid; idx < 2048; idx += 384) {
            int k = idx >> 5, f = idx & 31;
            cp16(xf + (k * 128 + f * 4) * 4, Xb + (size_t)(kt + k) * HW + n0 + f * 4);
        }
    };

    stage(0, 0);
    CP_COMMIT();

    for (int i = 0; i < PJ_NKT; i++) {
        const int cur = i & 1;
        CP_WAIT0();
        __syncthreads();

        if (i + 1 < PJ_NKT) {
            stage((i + 1) * 64, 1 - cur);
            CP_COMMIT();
        }

        {
            const float4* xf = (const float4*)(smem + PJ_XF_OFF + cur * 32768);
            __nv_bfloat16* XS = (__nv_bfloat16*)(smem + PJ_XS_OFF);
            for (int idx = tid; idx < 2048; idx += 384) {
                int k = idx >> 5, f = idx & 31;
                float4 v = xf[k * 32 + f];
                *(uint2*)&XS[k * 136 + f * 4] =
                    make_uint2(packbf(v.x, v.y), packbf(v.z, v.w));
            }
        }
        __syncthreads();

        const __nv_bfloat16* WB = (const __nv_bfloat16*)(smem + cur * 41472);
        const __nv_bfloat16* XS = (const __nv_bfloat16*)(smem + PJ_XS_OFF);
#pragma unroll
        for (int ks = 0; ks < 4; ks++) {
            uint32_t A3[3][4];
#pragma unroll
            for (int p = 0; p < 3; p++)
                ldsm_x4(A3[p], smem_u32(&WB[(p * 96 + arow) * 72 + ks * 16 + acol]));
#pragma unroll
            for (int dp = 0; dp < 4; dp++) {
                uint32_t Bf[4];
                ldsm_x4_t(Bf, smem_u32(&XS[(ks * 16 + trow) * 136 + tcol + dp * 16]));
#pragma unroll
                for (int p = 0; p < 3; p++) {
                    mma_bf16(Cacc[p][2 * dp], A3[p], Bf);
                    mma_bf16(Cacc[p][2 * dp + 1], A3[p], Bf + 2);
                }
            }
        }
    }

    const int r0 = mrow + (lane >> 2);
    const int c0 = n0 + nh + 2 * (lane & 3);
#pragma unroll
    for (int p = 0; p < 3; p++) {
        __nv_bfloat16* outp = ((p == 0) ? g_Qh : (p == 1) ? g_Kh : g_Vh) + (size_t)b * LL * DD;
#pragma unroll
        for (int d = 0; d < 8; d++) {
            *(uint32_t*)&outp[(size_t)r0 * HW + c0 + d * 8] = packbf(Cacc[p][d][0], Cacc[p][d][1]);
            *(uint32_t*)&outp[(size_t)(r0 + 8) * HW + c0 + d * 8] = packbf(Cacc[p][d][2], Cacc[p][d][3]);
        }
    }
}

// ---------------------------------------------------------------------------
// Tensor-core flash attention (mma.sync bf16), cp.async double-buffered K/V.
// BM=128, BN=64, 8 warps. grid: (LL/128, B), block 256. (unchanged from R9)
// ---------------------------------------------------------------------------
#define AQ_OFF 0
#define AK_OFF(buf) (18432 + (buf) * 9216)
#define AV_OFF(buf) (36864 + (buf) * 9216)
#define AT_SMEM 55296
#define AT_NIT  (LL / 64)

__global__ __launch_bounds__(256, 2) void attn_kernel()
{
    extern __shared__ char smem[];
    const uint32_t sb = smem_u32(smem);

    const int tid = threadIdx.x, warp = tid >> 5, lane = tid & 31;
    const int b = blockIdx.y;
    const int l0 = blockIdx.x * 128;

    const __nv_bfloat16* Qg = g_Qh + ((size_t)b * LL + l0) * DD;
    const __nv_bfloat16* Kg = g_Kh + (size_t)b * LL * DD;
    const __nv_bfloat16* Vg = g_Vh + (size_t)b * LL * DD;

    auto stageKV = [&](int kt, int buf) {
#pragma unroll
        for (int i = 0; i < 2; i++) {
            int v = tid + i * 256;
            int row = v >> 3, seg = v & 7;
            cp16(sb + AK_OFF(buf) + row * 144 + seg * 16, Kg + (size_t)(kt + row) * 64 + seg * 8);
            cp16(sb + AV_OFF(buf) + row * 144 + seg * 16, Vg + (size_t)(kt + row) * 64 + seg * 8);
        }
    };

#pragma unroll
    for (int i = 0; i < 4; i++) {
        int v = tid + i * 256;
        int row = v >> 3, seg = v & 7;
        cp16(sb + AQ_OFF + row * 144 + seg * 16, Qg + (size_t)row * 64 + seg * 8);
    }
    stageKV(0, 0);
    CP_COMMIT();
    CP_WAIT0();
    __syncthreads();

    uint32_t QF[4][4];
    {
        const __nv_bfloat16* Qs = (const __nv_bfloat16*)(smem + AQ_OFF);
        int r = warp * 16 + (lane & 15);
        int c = (lane >> 4) * 8;
#pragma unroll
        for (int ks = 0; ks < 4; ks++)
            ldsm_x4(QF[ks], smem_u32(&Qs[r * 72 + ks * 16 + c]));
    }

    float O[8][4];
#pragma unroll
    for (int d = 0; d < 8; d++)
#pragma unroll
        for (int q = 0; q < 4; q++) O[d][q] = 0.f;
    float lsum0 = 0.f, lsum1 = 0.f;

    const int krow = (lane & 7) + ((lane >> 4) << 3);
    const int kcol = ((lane >> 3) & 1) << 3;
    const int vrow = (lane & 7) + (((lane >> 3) & 1) << 3);
    const int vcol = (lane >> 4) << 3;

    for (int it = 0; it < AT_NIT; it++) {
        const int cur = it & 1;
        if (it + 1 < AT_NIT) {
            stageKV((it + 1) * 64, 1 - cur);
            CP_COMMIT();
        }

        const __nv_bfloat16* Ks = (const __nv_bfloat16*)(smem + AK_OFF(cur));
        const __nv_bfloat16* Vs = (const __nv_bfloat16*)(smem + AV_OFF(cur));

        float S[8][4];
#pragma unroll
        for (int j = 0; j < 8; j++)
#pragma unroll
            for (int q = 0; q < 4; q++) S[j][q] = 0.f;

#pragma unroll
        for (int jp = 0; jp < 4; jp++) {
#pragma unroll
            for (int ks = 0; ks < 4; ks++) {
                uint32_t KB[4];
                ldsm_x4(KB, smem_u32(&Ks[(jp * 16 + krow) * 72 + ks * 16 + kcol]));
                mma_bf16(S[2 * jp], QF[ks], KB);
                mma_bf16(S[2 * jp + 1], QF[ks], KB + 2);
            }
        }

        uint32_t PA[4][4];
#pragma unroll
        for (int jp = 0; jp < 4; jp++) {
            float e0 = __expf(S[2 * jp][0]), e1 = __expf(S[2 * jp][1]);
            float e2 = __expf(S[2 * jp][2]), e3 = __expf(S[2 * jp][3]);
            float f0 = __expf(S[2 * jp + 1][0]), f1 = __expf(S[2 * jp + 1][1]);
            float f2 = __expf(S[2 * jp + 1][2]), f3 = __expf(S[2 * jp + 1][3]);
            lsum0 += (e0 + e1) + (f0 + f1);
            lsum1 += (e2 + e3) + (f2 + f3);
            PA[jp][0] = packbf(e0, e1);
            PA[jp][1] = packbf(e2, e3);
            PA[jp][2] = packbf(f0, f1);
            PA[jp][3] = packbf(f2, f3);
        }

#pragma unroll
        for (int dp = 0; dp < 4; dp++) {
#pragma unroll
            for (int kk = 0; kk < 4; kk++) {
                uint32_t VB[4];
                ldsm_x4_t(VB, smem_u32(&Vs[(kk * 16 + vrow) * 72 + dp * 16 + vcol]));
                mma_bf16(O[2 * dp], PA[kk], VB);
                mma_bf16(O[2 * dp + 1], PA[kk], VB + 2);
            }
        }

        if (it + 1 < AT_NIT) {
            CP_WAIT0();
            __syncthreads();
        }
    }

    lsum0 += __shfl_xor_sync(0xffffffffu, lsum0, 1);
    lsum0 += __shfl_xor_sync(0xffffffffu, lsum0, 2);
    lsum1 += __shfl_xor_sync(0xffffffffu, lsum1, 1);
    lsum1 += __shfl_xor_sync(0xffffffffu, lsum1, 2);
    const float inv0 = 1.f / lsum0, inv1 = 1.f / lsum1;

    const int r0 = l0 + warp * 16 + (lane >> 2);
    const int col = 2 * (lane & 3);
    __nv_bfloat16* Ag = g_Ah + (size_t)b * LL * DD;
#pragma unroll
    for (int d = 0; d < 8; d++) {
        *(uint32_t*)&Ag[(size_t)r0 * 64 + d * 8 + col] = packbf(O[d][0] * inv0, O[d][1] * inv0);
        *(uint32_t*)&Ag[(size_t)(r0 + 8) * 64 + d * 8 + col] = packbf(O[d][2] * inv1, O[d][3] * inv1);
    }
}

// ---------------------------------------------------------------------------
// Output conv + gamma + residual. Tile 64(o) x 128(n); x residual PREFETCHED
// into registers before the mma loop so its DRAM latency overlaps staging+mma.
// grid: (HW/128, CC/64, B), block 256 (8 warps: 4 o-strips x 2 n-halves).
// ---------------------------------------------------------------------------
__global__ __launch_bounds__(256, 2) void outconv_kernel(
    const float* __restrict__ x,
    const float* __restrict__ gamma,
    float* __restrict__ out)
{
    __shared__ __nv_bfloat16 Wcs[64 * 104];  // [o][k] stride 104
    __shared__ __nv_bfloat16 As[96 * 136];   // [k][n] stride 136

    const int tid = threadIdx.x, warp = tid >> 5, lane = tid & 31;
    const int n0 = blockIdx.x * 128;
    const int o0 = blockIdx.y * 64;
    const int b = blockIdx.z;

    const __nv_bfloat16* Ab = g_Ah + (size_t)b * LL * DD;

    // stage Wc (64x96: 768 chunks) + A (96x128: 1536 chunks) via cp.async
#pragma unroll
    for (int idx = tid; idx < 768; idx += 256) {
        int o = idx / 12, f = idx - o * 12;
        cp16(smem_u32(&Wcs[o * 104 + f * 8]), g_Wch + (size_t)(o0 + o) * CK + f * 8);
    }
#pragma unroll
    for (int idx = tid; idx < 1536; idx += 256) {
        int k = idx >> 4, f = idx & 15;
        cp16(smem_u32(&As[k * 136 + f * 8]), Ab + (size_t)k * HW + n0 + f * 8);
    }
    CP_COMMIT();

    const int om = (warp & 3) * 16;
    const int nh = (warp >> 2) * 64;
    const int orow = o0 + om + (lane >> 2);
    const int c0 = n0 + nh + 2 * (lane & 3);
    const size_t base0 = ((size_t)b * CC + orow) * HW + c0;
    const size_t base1 = ((size_t)b * CC + orow + 8) * HW + c0;

    // Prefetch x residual (independent of staged data) — overlaps wait + mma.
    float2 xp0[8], xp1[8];
#pragma unroll
    for (int d = 0; d < 8; d++) {
        xp0[d] = *(const float2*)&x[base0 + d * 8];
        xp1[d] = *(const float2*)&x[base1 + d * 8];
    }

    CP_WAIT0();
    __syncthreads();

    float Cacc[8][4];
#pragma unroll
    for (int d = 0; d < 8; d++)
#pragma unroll
        for (int q = 0; q < 4; q++) Cacc[d][q] = 0.f;

    const int arow = om + (lane & 15), acol = (lane >> 4) << 3;
    const int trow = (lane & 7) + (((lane >> 3) & 1) << 3);
    const int tcol = nh + ((lane >> 4) << 3);

#pragma unroll
    for (int ks = 0; ks < 6; ks++) {
        uint32_t A[4];
        ldsm_x4(A, smem_u32(&Wcs[arow * 104 + ks * 16 + acol]));
#pragma unroll
        for (int dp = 0; dp < 4; dp++) {
            uint32_t Bf[4];
            ldsm_x4_t(Bf, smem_u32(&As[(ks * 16 + trow) * 136 + tcol + dp * 16]));
            mma_bf16(Cacc[2 * dp], A, Bf);
            mma_bf16(Cacc[2 * dp + 1], A, Bf + 2);
        }
    }

    const float g = gamma[0];
#pragma unroll
    for (int d = 0; d < 8; d++) {
        float2 v0 = make_float2(fmaf(g, Cacc[d][0], xp0[d].x), fmaf(g, Cacc[d][1], xp0[d].y));
        float2 v1 = make_float2(fmaf(g, Cacc[d][2], xp1[d].x), fmaf(g, Cacc[d][3], xp1[d].y));
        *(float2*)&out[base0 + d * 8] = v0;
        *(float2*)&out[base1 + d * 8] = v1;
    }
}

// ---------------------------------------------------------------------------
extern "C" void kernel_launch(void* const* d_in, const int* in_sizes, int n_in,
                              void* d_out, int out_size)
{
    const float* x  = (const float*)d_in[0];
    const float* Wq = (const float*)d_in[1];
    const float* Wk = (const float*)d_in[2];
    const float* Wv = (const float*)d_in[3];
    const float* Wc = (const float*)d_in[4];
    const float* gm = (const float*)d_in[5];
    float* out = (float*)d_out;

    prep_kernel<<<(3 * CK * CC + CC * CK + 255) / 256, 256>>>(Wq, Wk, Wv, Wc);

    cudaFuncSetAttribute(proj_kernel, cudaFuncAttributeMaxDynamicSharedMemorySize, PJ_SMEM);
    proj_kernel<<<dim3(HW / 128, 1, BB), 384, PJ_SMEM>>>(x);

    cudaFuncSetAttribute(attn_kernel, cudaFuncAttributeMaxDynamicSharedMemorySize, AT_SMEM);
    attn_kernel<<<dim3(LL / 128, BB), 256, AT_SMEM>>>();

    outconv_kernel<<<dim3(HW / 128, CC / 64, BB), 256>>>(x, gm, out);
}

// round 13
// speedup vs baseline: 1.0804x; 1.0804x over previous
#include <cuda_runtime.h>
#include <cuda_bf16.h>
#include <cstdint>

#define BB 8
#define CC 768
#define HW 4096
#define CK 96
#define LL 6144   // CK * H
#define DD 64     // = W

// Scratch (device globals; no allocation allowed)
__device__ __nv_bfloat16 g_Qh[BB * LL * DD];
__device__ __nv_bfloat16 g_Kh[BB * LL * DD];
__device__ __nv_bfloat16 g_Vh[BB * LL * DD];
__device__ __nv_bfloat16 g_Ah[BB * LL * DD];
__device__ __nv_bfloat16 g_Wh[3 * CK * CC];   // Wq,Wk,Wv in bf16
__device__ __nv_bfloat16 g_Wch[CC * CK];      // Wc in bf16

// ---------------------------------------------------------------------------
// Helpers
// ---------------------------------------------------------------------------
__device__ __forceinline__ uint32_t smem_u32(const void* p) {
    return (uint32_t)__cvta_generic_to_shared(p);
}
__device__ __forceinline__ void ldsm_x4(uint32_t d[4], uint32_t a) {
    asm volatile("ldmatrix.sync.aligned.m8n8.x4.shared.b16 {%0,%1,%2,%3},[%4];"
                 : "=r"(d[0]), "=r"(d[1]), "=r"(d[2]), "=r"(d[3]) : "r"(a));
}
__device__ __forceinline__ void ldsm_x4_t(uint32_t d[4], uint32_t a) {
    asm volatile("ldmatrix.sync.aligned.m8n8.x4.trans.shared.b16 {%0,%1,%2,%3},[%4];"
                 : "=r"(d[0]), "=r"(d[1]), "=r"(d[2]), "=r"(d[3]) : "r"(a));
}
__device__ __forceinline__ void mma_bf16(float c[4], const uint32_t a[4], const uint32_t b[2]) {
    asm volatile(
        "mma.sync.aligned.m16n8k16.row.col.f32.bf16.bf16.f32 "
        "{%0,%1,%2,%3},{%4,%5,%6,%7},{%8,%9},{%0,%1,%2,%3};"
        : "+f"(c[0]), "+f"(c[1]), "+f"(c[2]), "+f"(c[3])
        : "r"(a[0]), "r"(a[1]), "r"(a[2]), "r"(a[3]), "r"(b[0]), "r"(b[1]));
}
__device__ __forceinline__ uint32_t packbf(float a, float b) {
    __nv_bfloat162 t = __floats2bfloat162_rn(a, b);
    return *(uint32_t*)&t;
}
__device__ __forceinline__ void cp16(uint32_t dst, const void* src) {
    asm volatile("cp.async.cg.shared.global [%0],[%1],16;" :: "r"(dst), "l"(src));
}
#define CP_COMMIT() asm volatile("cp.async.commit_group;" ::: "memory")
#define CP_WAIT0()  asm volatile("cp.async.wait_group 0;" ::: "memory")

// ---------------------------------------------------------------------------
// Prep: convert weights to bf16 once
// ---------------------------------------------------------------------------
__global__ void prep_kernel(const float* __restrict__ Wq, const float* __restrict__ Wk,
                            const float* __restrict__ Wv, const float* __restrict__ Wc)
{
    int i = blockIdx.x * 256 + threadIdx.x;
    const int n1 = 3 * CK * CC;
    if (i < n1) {
        int p = i / (CK * CC), r = i % (CK * CC);
        const float* W = (p == 0) ? Wq : (p == 1) ? Wk : Wv;
        g_Wh[i] = __float2bfloat16(W[r]);
    } else if (i < n1 + CC * CK) {
        g_Wch[i - n1] = __float2bfloat16(Wc[i - n1]);
    }
}

// ---------------------------------------------------------------------------
// Fused projection, double-buffered cp.async pipeline. Per-batch grid (32,1,1).
// ---------------------------------------------------------------------------
#define PJ_XF_OFF 82944
#define PJ_XS_OFF 148480
#define PJ_SMEM   165888
#define PJ_NKT    12

__global__ __launch_bounds__(384) void proj_kernel(const float* __restrict__ x, int b)
{
    extern __shared__ char smem[];
    const uint32_t sb = smem_u32(smem);

    const int tid = threadIdx.x, warp = tid >> 5, lane = tid & 31;
    const int n0 = blockIdx.x * 128;
    const float* Xb = x + (size_t)b * CC * HW;

    const int mrow = (warp % 6) * 16;
    const int nh = (warp / 6) * 64;

    float Cacc[3][8][4];
#pragma unroll
    for (int p = 0; p < 3; p++)
#pragma unroll
        for (int d = 0; d < 8; d++)
#pragma unroll
            for (int q = 0; q < 4; q++) Cacc[p][d][q] = 0.f;

    const int arow = mrow + (lane & 15), acol = (lane >> 4) << 3;
    const int trow = (lane & 7) + (((lane >> 3) & 1) << 3);
    const int tcol = nh + ((lane >> 4) << 3);

    auto stage = [&](int kt, int buf) {
        const uint32_t wb = sb + buf * 41472;
        const uint32_t xf = sb + PJ_XF_OFF + buf * 32768;
#pragma unroll
        for (int idx = tid; idx < 2304; idx += 384) {
            int p = idx / 768, rem = idx - p * 768;
            int m = rem >> 3, f = rem & 7;
            cp16(wb + (p * 96 + m) * 144 + f * 16,
                 g_Wh + (size_t)(p * CK + m) * CC + kt + f * 8);
        }
        for (int idx = tid; idx < 2048; idx += 384) {
            int k = idx >> 5, f = idx & 31;
            cp16(xf + (k * 128 + f * 4) * 4, Xb + (size_t)(kt + k) * HW + n0 + f * 4);
        }
    };

    stage(0, 0);
    CP_COMMIT();

    for (int i = 0; i < PJ_NKT; i++) {
        const int cur = i & 1;
        CP_WAIT0();
        __syncthreads();

        if (i + 1 < PJ_NKT) {
            stage((i + 1) * 64, 1 - cur);
            CP_COMMIT();
        }

        {
            const float4* xf = (const float4*)(smem + PJ_XF_OFF + cur * 32768);
            __nv_bfloat16* XS = (__nv_bfloat16*)(smem + PJ_XS_OFF);
            for (int idx = tid; idx < 2048; idx += 384) {
                int k = idx >> 5, f = idx & 31;
                float4 v = xf[k * 32 + f];
                *(uint2*)&XS[k * 136 + f * 4] =
                    make_uint2(packbf(v.x, v.y), packbf(v.z, v.w));
            }
        }
        __syncthreads();

        const __nv_bfloat16* WB = (const __nv_bfloat16*)(smem + cur * 41472);
        const __nv_bfloat16* XS = (const __nv_bfloat16*)(smem + PJ_XS_OFF);
#pragma unroll
        for (int ks = 0; ks < 4; ks++) {
            uint32_t A3[3][4];
#pragma unroll
            for (int p = 0; p < 3; p++)
                ldsm_x4(A3[p], smem_u32(&WB[(p * 96 + arow) * 72 + ks * 16 + acol]));
#pragma unroll
            for (int dp = 0; dp < 4; dp++) {
                uint32_t Bf[4];
                ldsm_x4_t(Bf, smem_u32(&XS[(ks * 16 + trow) * 136 + tcol + dp * 16]));
#pragma unroll
                for (int p = 0; p < 3; p++) {
                    mma_bf16(Cacc[p][2 * dp], A3[p], Bf);
                    mma_bf16(Cacc[p][2 * dp + 1], A3[p], Bf + 2);
                }
            }
        }
    }

    const int r0 = mrow + (lane >> 2);
    const int c0 = n0 + nh + 2 * (lane & 3);
#pragma unroll
    for (int p = 0; p < 3; p++) {
        __nv_bfloat16* outp = ((p == 0) ? g_Qh : (p == 1) ? g_Kh : g_Vh) + (size_t)b * LL * DD;
#pragma unroll
        for (int d = 0; d < 8; d++) {
            *(uint32_t*)&outp[(size_t)r0 * HW + c0 + d * 8] = packbf(Cacc[p][d][0], Cacc[p][d][1]);
            *(uint32_t*)&outp[(size_t)(r0 + 8) * HW + c0 + d * 8] = packbf(Cacc[p][d][2], Cacc[p][d][3]);
        }
    }
}

// ---------------------------------------------------------------------------
// Tensor-core flash attention (mma.sync bf16), cp.async double-buffered K/V.
// BM=128, BN=64, 8 warps. Per-batch grid (48,1,1).
// ---------------------------------------------------------------------------
#define AQ_OFF 0
#define AK_OFF(buf) (18432 + (buf) * 9216)
#define AV_OFF(buf) (36864 + (buf) * 9216)
#define AT_SMEM 55296
#define AT_NIT  (LL / 64)

__global__ __launch_bounds__(256, 2) void attn_kernel(int b)
{
    extern __shared__ char smem[];
    const uint32_t sb = smem_u32(smem);

    const int tid = threadIdx.x, warp = tid >> 5, lane = tid & 31;
    const int l0 = blockIdx.x * 128;

    const __nv_bfloat16* Qg = g_Qh + ((size_t)b * LL + l0) * DD;
    const __nv_bfloat16* Kg = g_Kh + (size_t)b * LL * DD;
    const __nv_bfloat16* Vg = g_Vh + (size_t)b * LL * DD;

    auto stageKV = [&](int kt, int buf) {
#pragma unroll
        for (int i = 0; i < 2; i++) {
            int v = tid + i * 256;
            int row = v >> 3, seg = v & 7;
            cp16(sb + AK_OFF(buf) + row * 144 + seg * 16, Kg + (size_t)(kt + row) * 64 + seg * 8);
            cp16(sb + AV_OFF(buf) + row * 144 + seg * 16, Vg + (size_t)(kt + row) * 64 + seg * 8);
        }
    };

#pragma unroll
    for (int i = 0; i < 4; i++) {
        int v = tid + i * 256;
        int row = v >> 3, seg = v & 7;
        cp16(sb + AQ_OFF + row * 144 + seg * 16, Qg + (size_t)row * 64 + seg * 8);
    }
    stageKV(0, 0);
    CP_COMMIT();
    CP_WAIT0();
    __syncthreads();

    uint32_t QF[4][4];
    {
        const __nv_bfloat16* Qs = (const __nv_bfloat16*)(smem + AQ_OFF);
        int r = warp * 16 + (lane & 15);
        int c = (lane >> 4) * 8;
#pragma unroll
        for (int ks = 0; ks < 4; ks++)
            ldsm_x4(QF[ks], smem_u32(&Qs[r * 72 + ks * 16 + c]));
    }

    float O[8][4];
#pragma unroll
    for (int d = 0; d < 8; d++)
#pragma unroll
        for (int q = 0; q < 4; q++) O[d][q] = 0.f;
    float lsum0 = 0.f, lsum1 = 0.f;

    const int krow = (lane & 7) + ((lane >> 4) << 3);
    const int kcol = ((lane >> 3) & 1) << 3;
    const int vrow = (lane & 7) + (((lane >> 3) & 1) << 3);
    const int vcol = (lane >> 4) << 3;

    for (int it = 0; it < AT_NIT; it++) {
        const int cur = it & 1;
        if (it + 1 < AT_NIT) {
            stageKV((it + 1) * 64, 1 - cur);
            CP_COMMIT();
        }

        const __nv_bfloat16* Ks = (const __nv_bfloat16*)(smem + AK_OFF(cur));
        const __nv_bfloat16* Vs = (const __nv_bfloat16*)(smem + AV_OFF(cur));

        float S[8][4];
#pragma unroll
        for (int j = 0; j < 8; j++)
#pragma unroll
            for (int q = 0; q < 4; q++) S[j][q] = 0.f;

#pragma unroll
        for (int jp = 0; jp < 4; jp++) {
#pragma unroll
            for (int ks = 0; ks < 4; ks++) {
                uint32_t KB[4];
                ldsm_x4(KB, smem_u32(&Ks[(jp * 16 + krow) * 72 + ks * 16 + kcol]));
                mma_bf16(S[2 * jp], QF[ks], KB);
                mma_bf16(S[2 * jp + 1], QF[ks], KB + 2);
            }
        }

        uint32_t PA[4][4];
#pragma unroll
        for (int jp = 0; jp < 4; jp++) {
            float e0 = __expf(S[2 * jp][0]), e1 = __expf(S[2 * jp][1]);
            float e2 = __expf(S[2 * jp][2]), e3 = __expf(S[2 * jp][3]);
            float f0 = __expf(S[2 * jp + 1][0]), f1 = __expf(S[2 * jp + 1][1]);
            float f2 = __expf(S[2 * jp + 1][2]), f3 = __expf(S[2 * jp + 1][3]);
            lsum0 += (e0 + e1) + (f0 + f1);
            lsum1 += (e2 + e3) + (f2 + f3);
            PA[jp][0] = packbf(e0, e1);
            PA[jp][1] = packbf(e2, e3);
            PA[jp][2] = packbf(f0, f1);
            PA[jp][3] = packbf(f2, f3);
        }

#pragma unroll
        for (int dp = 0; dp < 4; dp++) {
#pragma unroll
            for (int kk = 0; kk < 4; kk++) {
                uint32_t VB[4];
                ldsm_x4_t(VB, smem_u32(&Vs[(kk * 16 + vrow) * 72 + dp * 16 + vcol]));
                mma_bf16(O[2 * dp], PA[kk], VB);
                mma_bf16(O[2 * dp + 1], PA[kk], VB + 2);
            }
        }

        if (it + 1 < AT_NIT) {
            CP_WAIT0();
            __syncthreads();
        }
    }

    lsum0 += __shfl_xor_sync(0xffffffffu, lsum0, 1);
    lsum0 += __shfl_xor_sync(0xffffffffu, lsum0, 2);
    lsum1 += __shfl_xor_sync(0xffffffffu, lsum1, 1);
    lsum1 += __shfl_xor_sync(0xffffffffu, lsum1, 2);
    const float inv0 = 1.f / lsum0, inv1 = 1.f / lsum1;

    const int r0 = l0 + warp * 16 + (lane >> 2);
    const int col = 2 * (lane & 3);
    __nv_bfloat16* Ag = g_Ah + (size_t)b * LL * DD;
#pragma unroll
    for (int d = 0; d < 8; d++) {
        *(uint32_t*)&Ag[(size_t)r0 * 64 + d * 8 + col] = packbf(O[d][0] * inv0, O[d][1] * inv0);
        *(uint32_t*)&Ag[(size_t)(r0 + 8) * 64 + d * 8 + col] = packbf(O[d][2] * inv1, O[d][3] * inv1);
    }
}

// ---------------------------------------------------------------------------
// Output conv + gamma + residual (R9-exact 128x128 tile). Per-batch grid (32,6).
// ---------------------------------------------------------------------------
__global__ __launch_bounds__(256, 2) void outconv_kernel(
    const float* __restrict__ x,
    const float* __restrict__ gamma,
    float* __restrict__ out, int b)
{
    __shared__ __nv_bfloat16 Wcs[128 * 104];
    __shared__ __nv_bfloat16 As[96 * 136];

    const int tid = threadIdx.x, warp = tid >> 5, lane = tid & 31;
    const int n0 = blockIdx.x * 128;
    const int o0 = blockIdx.y * 128;

    const __nv_bfloat16* Ab = g_Ah + (size_t)b * LL * DD;

#pragma unroll
    for (int idx = tid; idx < 1536; idx += 256) {
        int o = idx / 12, f = idx - o * 12;
        cp16(smem_u32(&Wcs[o * 104 + f * 8]), g_Wch + (size_t)(o0 + o) * CK + f * 8);
    }
#pragma unroll
    for (int idx = tid; idx < 1536; idx += 256) {
        int k = idx >> 4, f = idx & 15;
        cp16(smem_u32(&As[k * 136 + f * 8]), Ab + (size_t)k * HW + n0 + f * 8);
    }
    CP_COMMIT();
    CP_WAIT0();
    __syncthreads();

    const int wm = warp & 3, wn = warp >> 2;
    const int om = wm * 32;
    const int nh = wn * 64;

    float Cacc[2][8][4];
#pragma unroll
    for (int s = 0; s < 2; s++)
#pragma unroll
        for (int d = 0; d < 8; d++)
#pragma unroll
            for (int q = 0; q < 4; q++) Cacc[s][d][q] = 0.f;

    const int arow = (lane & 15), acol = (lane >> 4) << 3;
    const int trow = (lane & 7) + (((lane >> 3) & 1) << 3);
    const int tcol = nh + ((lane >> 4) << 3);

#pragma unroll
    for (int ks = 0; ks < 6; ks++) {
        uint32_t Bf[4][4];
#pragma unroll
        for (int dp = 0; dp < 4; dp++)
            ldsm_x4_t(Bf[dp], smem_u32(&As[(ks * 16 + trow) * 136 + tcol + dp * 16]));
#pragma unroll
        for (int s = 0; s < 2; s++) {
            uint32_t A[4];
            ldsm_x4(A, smem_u32(&Wcs[(om + s * 16 + arow) * 104 + ks * 16 + acol]));
#pragma unroll
            for (int dp = 0; dp < 4; dp++) {
                mma_bf16(Cacc[s][2 * dp], A, Bf[dp]);
                mma_bf16(Cacc[s][2 * dp + 1], A, Bf[dp] + 2);
            }
        }
    }

    const float g = gamma[0];
#pragma unroll
    for (int s = 0; s < 2; s++) {
        const int orow = o0 + om + s * 16 + (lane >> 2);
        const int c0 = n0 + nh + 2 * (lane & 3);
#pragma unroll
        for (int d = 0; d < 8; d++) {
            size_t off0 = ((size_t)b * CC + orow) * HW + c0 + d * 8;
            size_t off1 = ((size_t)b * CC + orow + 8) * HW + c0 + d * 8;
            float2 x0 = *(const float2*)&x[off0];
            float2 x1 = *(const float2*)&x[off1];
            float2 v0 = make_float2(fmaf(g, Cacc[s][d][0], x0.x), fmaf(g, Cacc[s][d][1], x0.y));
            float2 v1 = make_float2(fmaf(g, Cacc[s][d][2], x1.x), fmaf(g, Cacc[s][d][3], x1.y));
            *(float2*)&out[off0] = v0;
            *(float2*)&out[off1] = v1;
        }
    }
}

// ---------------------------------------------------------------------------
// Stream/event resources: created once at program load (host-side objects,
// no device-memory allocation; kernel_launch itself stays guard-free and
// does identical work on every call).
// ---------------------------------------------------------------------------
struct GraphStreams {
    cudaStream_t s[BB];
    cudaEvent_t e0, eb[BB];
    GraphStreams() {
        for (int i = 0; i < BB; i++) cudaStreamCreateWithFlags(&s[i], cudaStreamNonBlocking);
        cudaEventCreateWithFlags(&e0, cudaEventDisableTiming);
        for (int i = 0; i < BB; i++) cudaEventCreateWithFlags(&eb[i], cudaEventDisableTiming);
    }
};
static GraphStreams g_gs;

// ---------------------------------------------------------------------------
extern "C" void kernel_launch(void* const* d_in, const int* in_sizes, int n_in,
                              void* d_out, int out_size)
{
    const float* x  = (const float*)d_in[0];
    const float* Wq = (const float*)d_in[1];
    const float* Wk = (const float*)d_in[2];
    const float* Wv = (const float*)d_in[3];
    const float* Wc = (const float*)d_in[4];
    const float* gm = (const float*)d_in[5];
    float* out = (float*)d_out;

    cudaFuncSetAttribute(proj_kernel, cudaFuncAttributeMaxDynamicSharedMemorySize, PJ_SMEM);
    cudaFuncSetAttribute(attn_kernel, cudaFuncAttributeMaxDynamicSharedMemorySize, AT_SMEM);

    // prep on the capture (default) stream, then fork 8 per-batch chains.
    prep_kernel<<<(3 * CK * CC + CC * CK + 255) / 256, 256>>>(Wq, Wk, Wv, Wc);
    cudaEventRecord(g_gs.e0, 0);

    for (int b = 0; b < BB; b++) {
        cudaStreamWaitEvent(g_gs.s[b], g_gs.e0, 0);
        proj_kernel<<<dim3(HW / 128, 1, 1), 384, PJ_SMEM, g_gs.s[b]>>>(x, b);
        attn_kernel<<<dim3(LL / 128, 1, 1), 256, AT_SMEM, g_gs.s[b]>>>(b);
        outconv_kernel<<<dim3(HW / 128, CC / 128, 1), 256, 0, g_gs.s[b]>>>(x, gm, out, b);
        cudaEventRecord(g_gs.eb[b], g_gs.s[b]);
        cudaStreamWaitEvent(0, g_gs.eb[b], 0);
    }
}